// round 11
// baseline (speedup 1.0000x reference)
#include <cuda_runtime.h>
#include <math.h>

// Problem constants
#define NB   4
#define C    256
#define H    64
#define W    64
#define HW   4096
#define NPIX 16384
#define G    8
#define GC   32
#define P    9
#define NOFF 144
#define NMSK 72

// GEMM tiling: BM=64, BN=128, BK=32; 8 warps, warp tile 32x32
#define BM 64
#define BN 128
#define BK 32
#define PADT 136

#define HALF_PIX (NPIX / 2)

// -------- scratch --------
__device__ float g_dw   [NPIX * C];
__device__ float g_xproj[NPIX * C];
__device__ float g_x1   [NPIX * C];
__device__ float g_off  [NPIX * NOFF];
__device__ float g_mlog [NPIX * NMSK];
__device__ float g_agg  [NPIX * C];

__device__ __forceinline__ unsigned f2tf(float f) {
    unsigned r; asm("cvt.rna.tf32.f32 %0, %1;" : "=r"(r) : "f"(f)); return r;
}

// ============================================================
// tf32 mma.sync GEMM core, 64x128x32 tiles.
// LAYOUT 0: A k-major source, PRE-OFFSET: element (k,m) at Asrc[k*HW + m]
// LAYOUT 1: A m-major source, PRE-OFFSET: element (m,k) at Asrc[m*256 + k]
// MODE   0: dense B0[256 x 256]
// MODE   1: B = concat(B0[256x144], B1[256x72]); cols >= 216 zero
// ============================================================
template<int LAYOUT, int MODE>
__device__ __forceinline__ void gemm_core(
    const float* __restrict__ Asrc,
    const float* __restrict__ B0, const float* __restrict__ B1,
    int bn, float acc[2][4][4])
{
    __shared__ float As[BK][PADT];
    __shared__ float Bs[BK][PADT];
    const int tid  = threadIdx.x;
    const int warp = tid >> 5, lane = tid & 31;
    const int gid  = lane >> 2, tig = lane & 3;
    const int wm   = warp >> 2, wn = warp & 3;

    float4 aReg[2], bReg[4];

    auto loadAB = [&](int k0) {
        #pragma unroll
        for (int i = 0; i < 2; i++) {
            if (LAYOUT == 0) {
                int idx = tid + 256 * i;          // 512 float4: 32 k-rows x 16 chunks
                int kr = idx >> 4, c = idx & 15;
                aReg[i] = *reinterpret_cast<const float4*>(
                    &Asrc[(size_t)(k0 + kr) * HW + c * 4]);
            } else {
                // m = lane + 32*i (0..63), k-chunk = warp*4
                aReg[i] = *reinterpret_cast<const float4*>(
                    &Asrc[(size_t)(lane + 32 * i) * 256 + k0 + warp * 4]);
            }
        }
        #pragma unroll
        for (int i = 0; i < 4; i++) {
            int k = k0 + warp + 8 * i;
            if (MODE == 0) {
                bReg[i] = *reinterpret_cast<const float4*>(&B0[(size_t)k * 256 + bn + lane * 4]);
            } else {
                int c = bn + lane * 4;
                if (c < NOFF)
                    bReg[i] = *reinterpret_cast<const float4*>(&B0[(size_t)k * NOFF + c]);
                else if (c < NOFF + NMSK)
                    bReg[i] = *reinterpret_cast<const float4*>(&B1[(size_t)k * NMSK + c - NOFF]);
                else
                    bReg[i] = make_float4(0.f, 0.f, 0.f, 0.f);
            }
        }
    };

    auto stage = [&]() {
        #pragma unroll
        for (int i = 0; i < 2; i++) {
            if (LAYOUT == 0) {
                int idx = tid + 256 * i;
                int kr = idx >> 4, c = idx & 15;
                float4 t;
                t.x = __uint_as_float(f2tf(aReg[i].x));
                t.y = __uint_as_float(f2tf(aReg[i].y));
                t.z = __uint_as_float(f2tf(aReg[i].z));
                t.w = __uint_as_float(f2tf(aReg[i].w));
                *reinterpret_cast<float4*>(&As[kr][c * 4]) = t;
            } else {
                int m = lane + 32 * i;
                As[warp * 4 + 0][m] = __uint_as_float(f2tf(aReg[i].x));
                As[warp * 4 + 1][m] = __uint_as_float(f2tf(aReg[i].y));
                As[warp * 4 + 2][m] = __uint_as_float(f2tf(aReg[i].z));
                As[warp * 4 + 3][m] = __uint_as_float(f2tf(aReg[i].w));
            }
        }
        #pragma unroll
        for (int i = 0; i < 4; i++) {
            float4 bt;
            bt.x = __uint_as_float(f2tf(bReg[i].x));
            bt.y = __uint_as_float(f2tf(bReg[i].y));
            bt.z = __uint_as_float(f2tf(bReg[i].z));
            bt.w = __uint_as_float(f2tf(bReg[i].w));
            *reinterpret_cast<float4*>(&Bs[warp + 8 * i][lane * 4]) = bt;
        }
    };

    loadAB(0);
    for (int k0 = 0; k0 < 256; k0 += BK) {
        __syncthreads();
        stage();
        __syncthreads();
        if (k0 + BK < 256) loadAB(k0 + BK);
        #pragma unroll
        for (int ks = 0; ks < 4; ks++) {
            unsigned a[2][4], b[4][2];
            #pragma unroll
            for (int mf = 0; mf < 2; mf++) {
                int m0 = wm * 32 + mf * 16;
                a[mf][0] = __float_as_uint(As[ks * 8 + tig    ][m0 + gid    ]);
                a[mf][1] = __float_as_uint(As[ks * 8 + tig    ][m0 + gid + 8]);
                a[mf][2] = __float_as_uint(As[ks * 8 + tig + 4][m0 + gid    ]);
                a[mf][3] = __float_as_uint(As[ks * 8 + tig + 4][m0 + gid + 8]);
            }
            #pragma unroll
            for (int nf = 0; nf < 4; nf++) {
                int n0 = wn * 32 + nf * 8;
                b[nf][0] = __float_as_uint(Bs[ks * 8 + tig    ][n0 + gid]);
                b[nf][1] = __float_as_uint(Bs[ks * 8 + tig + 4][n0 + gid]);
            }
            #pragma unroll
            for (int mf = 0; mf < 2; mf++)
                #pragma unroll
                for (int nf = 0; nf < 4; nf++)
                    asm volatile(
                        "mma.sync.aligned.m16n8k8.row.col.f32.tf32.tf32.f32 "
                        "{%0,%1,%2,%3},{%4,%5,%6,%7},{%8,%9},{%0,%1,%2,%3};"
                        : "+f"(acc[mf][nf][0]), "+f"(acc[mf][nf][1]),
                          "+f"(acc[mf][nf][2]), "+f"(acc[mf][nf][3])
                        : "r"(a[mf][0]), "r"(a[mf][1]), "r"(a[mf][2]), "r"(a[mf][3]),
                          "r"(b[nf][0]), "r"(b[nf][1]));
        }
    }
}

// ---- input projection: x(NCHW) @ w_in + b_in -> g_xproj (NHWC) ----
extern "C" __global__ void __launch_bounds__(256)
gemm_in_kernel(const float* __restrict__ x,
               const float* __restrict__ Bw, const float* __restrict__ bias)
{
    float acc[2][4][4] = {};
    const int bm = blockIdx.y * BM, bn = blockIdx.x * BN;
    const int n = bm >> 12, hw0 = bm & 4095;
    gemm_core<0, 0>(x + (size_t)n * C * HW + hw0, Bw, nullptr, bn, acc);

    const int lane = threadIdx.x & 31, warp = threadIdx.x >> 5;
    const int gid = lane >> 2, tig = lane & 3, wm = warp >> 2, wn = warp & 3;
    #pragma unroll
    for (int mf = 0; mf < 2; mf++) {
        int r0 = bm + wm * 32 + mf * 16 + gid;
        #pragma unroll
        for (int nf = 0; nf < 4; nf++) {
            int col = bn + wn * 32 + nf * 8 + 2 * tig;
            float bx = bias[col], by = bias[col + 1];
            float2 lo = {acc[mf][nf][0] + bx, acc[mf][nf][1] + by};
            float2 hi = {acc[mf][nf][2] + bx, acc[mf][nf][3] + by};
            *reinterpret_cast<float2*>(&g_xproj[(size_t)r0 * 256 + col])       = lo;
            *reinterpret_cast<float2*>(&g_xproj[(size_t)(r0 + 8) * 256 + col]) = hi;
        }
    }
}

// ---- fused offset+mask projection (bm_base for half-grids) ----
extern "C" __global__ void __launch_bounds__(256)
gemm_offmask_kernel(const float* __restrict__ Bo, const float* __restrict__ Bm,
                    const float* __restrict__ bo, const float* __restrict__ bmk,
                    int bm_base)
{
    float acc[2][4][4] = {};
    const int bm = bm_base + blockIdx.y * BM, bn = blockIdx.x * BN;
    gemm_core<1, 1>(g_x1 + (size_t)bm * 256, Bo, Bm, bn, acc);

    const int lane = threadIdx.x & 31, warp = threadIdx.x >> 5;
    const int gid = lane >> 2, tig = lane & 3, wm = warp >> 2, wn = warp & 3;
    #pragma unroll
    for (int mf = 0; mf < 2; mf++) {
        int r0 = bm + wm * 32 + mf * 16 + gid;
        #pragma unroll
        for (int nf = 0; nf < 4; nf++) {
            int col = bn + wn * 32 + nf * 8 + 2 * tig;
            if (col >= NOFF + NMSK) continue;
            float bx, by; float *d0, *d1;
            if (col < NOFF) {
                bx = bo[col]; by = bo[col + 1];
                d0 = &g_off[(size_t)r0 * NOFF + col];
                d1 = &g_off[(size_t)(r0 + 8) * NOFF + col];
            } else {
                int mc = col - NOFF;
                bx = bmk[mc]; by = bmk[mc + 1];
                d0 = &g_mlog[(size_t)r0 * NMSK + mc];
                d1 = &g_mlog[(size_t)(r0 + 8) * NMSK + mc];
            }
            float2 lo = {acc[mf][nf][0] + bx, acc[mf][nf][1] + by};
            float2 hi = {acc[mf][nf][2] + bx, acc[mf][nf][3] + by};
            *reinterpret_cast<float2*>(d0) = lo;
            *reinterpret_cast<float2*>(d1) = hi;
        }
    }
}

// ---- output projection + bias + BN + SiLU -> NCHW (bm_base) ----
extern "C" __global__ void __launch_bounds__(256)
gemm_out_kernel(const float* __restrict__ Bw, const float* __restrict__ bias,
                const float* __restrict__ bn_g, const float* __restrict__ bn_b,
                const float* __restrict__ bn_mean, const float* __restrict__ bn_var,
                float* __restrict__ out, int bm_base)
{
    float acc[2][4][4] = {};
    const int bm = bm_base + blockIdx.y * BM, bn = blockIdx.x * BN;
    gemm_core<1, 0>(g_agg + (size_t)bm * 256, Bw, nullptr, bn, acc);

    const int lane = threadIdx.x & 31, warp = threadIdx.x >> 5;
    const int gid = lane >> 2, tig = lane & 3, wm = warp >> 2, wn = warp & 3;
    #pragma unroll
    for (int nf = 0; nf < 4; nf++) {
        int colb = bn + wn * 32 + nf * 8 + 2 * tig;
        #pragma unroll
        for (int j = 0; j < 2; j++) {
            int col = colb + j;
            float sc = bn_g[col] * rsqrtf(bn_var[col] + 1e-5f);
            float sh = bn_b[col] - bn_mean[col] * sc;
            float bo = bias[col];
            #pragma unroll
            for (int mf = 0; mf < 2; mf++) {
                #pragma unroll
                for (int h2 = 0; h2 < 2; h2++) {
                    int row = bm + wm * 32 + mf * 16 + gid + 8 * h2;
                    float v = acc[mf][nf][2 * h2 + j] + bo;
                    v = v * sc + sh;
                    v = v / (1.f + expf(-v));
                    int n = row >> 12, hw = row & 4095;
                    out[((size_t)n * C + col) * HW + hw] = v;
                }
            }
        }
    }
}

// ============================================================
// Depthwise 3x3 conv, NCHW-native.
// ============================================================
extern "C" __global__ void __launch_bounds__(256)
dwconv_kernel(const float* __restrict__ x,
              const float* __restrict__ w_dw, const float* __restrict__ b_dw)
{
    __shared__ float sp[HW];
    const int n = blockIdx.x >> 8, c = blockIdx.x & 255;
    const int tid = threadIdx.x;
    const float* src = x + ((size_t)n * C + c) * HW;

    #pragma unroll
    for (int i = 0; i < 4; i++)
        *reinterpret_cast<float4*>(&sp[(tid + 256 * i) * 4]) =
            *reinterpret_cast<const float4*>(&src[(tid + 256 * i) * 4]);

    float wk[9];
    #pragma unroll
    for (int i = 0; i < 9; i++) wk[i] = w_dw[c * 9 + i];
    const float bb = b_dw[c];
    __syncthreads();

    float* dst = g_dw + ((size_t)n * C + c) * HW;
    #pragma unroll
    for (int i = 0; i < 16; i++) {
        int hw = tid + 256 * i;
        int h = hw >> 6, w = hw & 63;
        float acc = bb;
        #pragma unroll
        for (int ky = 0; ky < 3; ky++) {
            int yy = h + ky - 1;
            if (yy < 0 || yy > 63) continue;
            #pragma unroll
            for (int kx = 0; kx < 3; kx++) {
                int xx = w + kx - 1;
                if (xx < 0 || xx > 63) continue;
                acc += sp[yy * 64 + xx] * wk[ky * 3 + kx];
            }
        }
        dst[hw] = acc;
    }
}

// ============================================================
// LayerNorm + exact GELU + NCHW->NHWC transpose.
// ============================================================
extern "C" __global__ void __launch_bounds__(256)
lnT_kernel(const float* __restrict__ ln_g, const float* __restrict__ ln_b)
{
    __shared__ float t[256][33];
    __shared__ float smean[32], sivar[32];
    const int n   = blockIdx.x >> 7;
    const int hw0 = (blockIdx.x & 127) * 32;
    const int tid = threadIdx.x;
    const int lane = tid & 31, wp = tid >> 5;

    const float* src = g_dw + (size_t)n * C * HW + hw0;
    #pragma unroll
    for (int r = 0; r < 32; r++) {
        int c = wp + 8 * r;
        t[c][lane] = src[(size_t)c * HW + lane];
    }
    __syncthreads();

    #pragma unroll
    for (int q = 0; q < 4; q++) {
        int p = wp * 4 + q;
        float s = 0.f;
        #pragma unroll
        for (int j = 0; j < 8; j++) s += t[lane + 32 * j][p];
        #pragma unroll
        for (int o = 16; o; o >>= 1) s += __shfl_xor_sync(0xffffffffu, s, o);
        float mu = s * (1.f / 256.f);
        float v = 0.f;
        #pragma unroll
        for (int j = 0; j < 8; j++) { float d = t[lane + 32 * j][p] - mu; v += d * d; }
        #pragma unroll
        for (int o = 16; o; o >>= 1) v += __shfl_xor_sync(0xffffffffu, v, o);
        if (lane == 0) { smean[p] = mu; sivar[p] = rsqrtf(v * (1.f / 256.f) + 1e-5f); }
    }
    __syncthreads();

    const float lg = ln_g[tid], lb = ln_b[tid];
    const size_t pixbase = (size_t)n * HW + hw0;
    #pragma unroll
    for (int p = 0; p < 32; p++) {
        float v = (t[tid][p] - smean[p]) * sivar[p] * lg + lb;
        float ge = 0.5f * v * (1.f + erff(v * 0.70710678118654752f));
        g_x1[(pixbase + p) * C + tid] = ge;
    }
}

// ============================================================
// Deformable sampling + softmax aggregation (pix_base for halves)
// ============================================================
extern "C" __global__ void __launch_bounds__(256)
sample_kernel(int pix_base)
{
    const int pix = pix_base + blockIdx.x;
    const int t   = threadIdx.x;
    const int g   = t >> 5, cc = t & 31;
    const int n = pix >> 12, hw = pix & 4095, h = hw >> 6, w = hw & 63;

    const float* ob = g_off  + (size_t)pix * NOFF + g * 18;
    const float* lb = g_mlog + (size_t)pix * NMSK + g * 9;

    float l[9], m = -1e30f;
    #pragma unroll
    for (int p = 0; p < 9; p++) { l[p] = lb[p]; m = fmaxf(m, l[p]); }
    float se = 0.f;
    #pragma unroll
    for (int p = 0; p < 9; p++) { l[p] = expf(l[p] - m); se += l[p]; }
    const float inv = 1.f / se;

    const float* base = g_xproj + (size_t)n * HW * C + g * GC + cc;
    float acc = 0.f;
    #pragma unroll
    for (int p = 0; p < 9; p++) {
        float gx = (float)(w + (p / 3)) + ob[2 * p + 0];
        float gy = (float)(h + (p % 3)) + ob[2 * p + 1];
        float x0f = floorf(gx), y0f = floorf(gy);
        int   x0 = (int)x0f, y0 = (int)y0f;
        float wx = gx - x0f, wy = gy - y0f;
        float w00 = (1.f - wx) * (1.f - wy);
        float w10 = wx * (1.f - wy);
        float w01 = (1.f - wx) * wy;
        float w11 = wx * wy;
        bool yi0 = (y0     >= 1 && y0     <= 64);
        bool yi1 = (y0 + 1 >= 1 && y0 + 1 <= 64);
        bool xi0 = (x0     >= 1 && x0     <= 64);
        bool xi1 = (x0 + 1 >= 1 && x0 + 1 <= 64);
        float v00 = 0.f, v10 = 0.f, v01 = 0.f, v11 = 0.f;
        if (yi0 && xi0) v00 = base[((size_t)(y0 - 1) * 64 + (x0 - 1)) * C];
        if (yi0 && xi1) v10 = base[((size_t)(y0 - 1) * 64 + (x0    )) * C];
        if (yi1 && xi0) v01 = base[((size_t)(y0    ) * 64 + (x0 - 1)) * C];
        if (yi1 && xi1) v11 = base[((size_t)(y0    ) * 64 + (x0    )) * C];
        acc += (l[p] * inv) * (w00 * v00 + w10 * v10 + w01 * v01 + w11 * v11);
    }
    g_agg[(size_t)pix * C + t] = acc;
}

// ============================================================
// launch: two-stream half-pipeline (R10 schedule)
// ============================================================
extern "C" void kernel_launch(void* const* d_in, const int* in_sizes, int n_in,
                              void* d_out, int out_size)
{
    const float* x       = (const float*)d_in[0];
    const float* w_in    = (const float*)d_in[1];
    const float* b_in    = (const float*)d_in[2];
    const float* w_dw    = (const float*)d_in[3];
    const float* b_dw    = (const float*)d_in[4];
    const float* ln_g    = (const float*)d_in[5];
    const float* ln_b    = (const float*)d_in[6];
    const float* w_off   = (const float*)d_in[7];
    const float* b_off   = (const float*)d_in[8];
    const float* w_mask  = (const float*)d_in[9];
    const float* b_mask  = (const float*)d_in[10];
    const float* w_out   = (const float*)d_in[11];
    const float* b_out   = (const float*)d_in[12];
    const float* bn_g    = (const float*)d_in[13];
    const float* bn_b    = (const float*)d_in[14];
    const float* bn_mean = (const float*)d_in[15];
    const float* bn_var  = (const float*)d_in[16];
    float* out = (float*)d_out;

    static cudaStream_t s2 = nullptr;
    static cudaEvent_t evA = nullptr, evB = nullptr, evL = nullptr, evE = nullptr;
    if (!s2) {
        cudaStreamCreateWithFlags(&s2, cudaStreamNonBlocking);
        cudaEventCreateWithFlags(&evA, cudaEventDisableTiming);
        cudaEventCreateWithFlags(&evB, cudaEventDisableTiming);
        cudaEventCreateWithFlags(&evL, cudaEventDisableTiming);
        cudaEventCreateWithFlags(&evE, cudaEventDisableTiming);
    }

    const dim3 gOffHalf(2, HALF_PIX / BM);       // (2, 128)
    const dim3 gOutHalf(C / BN, HALF_PIX / BM);  // (2, 128)

    // fork: gemm_in depends only on x
    cudaEventRecord(evA, 0);
    cudaStreamWaitEvent(s2, evA, 0);
    gemm_in_kernel<<<dim3(C / BN, NPIX / BM), 256, 0, s2>>>(x, w_in, b_in);
    cudaEventRecord(evB, s2);

    // s0: dw branch
    dwconv_kernel<<<NB * C, 256>>>(x, w_dw, b_dw);
    lnT_kernel   <<<NPIX / 32, 256>>>(ln_g, ln_b);
    cudaEventRecord(evL, 0);

    // s0: half 0 chain
    gemm_offmask_kernel<<<gOffHalf, 256>>>(w_off, w_mask, b_off, b_mask, 0);
    cudaStreamWaitEvent(0, evB, 0);
    sample_kernel  <<<HALF_PIX, 256>>>(0);
    gemm_out_kernel<<<gOutHalf, 256>>>(w_out, b_out, bn_g, bn_b, bn_mean, bn_var,
                                       out, 0);

    // s2: half 1 chain (after lnT; gemm_in already in-stream)
    cudaStreamWaitEvent(s2, evL, 0);
    gemm_offmask_kernel<<<gOffHalf, 256, 0, s2>>>(w_off, w_mask, b_off, b_mask, HALF_PIX);
    sample_kernel  <<<HALF_PIX, 256, 0, s2>>>(HALF_PIX);
    gemm_out_kernel<<<gOutHalf, 256, 0, s2>>>(w_out, b_out, bn_g, bn_b, bn_mean, bn_var,
                                              out, HALF_PIX);
    cudaEventRecord(evE, s2);

    // join
    cudaStreamWaitEvent(0, evE, 0);
}

// round 16
// speedup vs baseline: 1.0388x; 1.0388x over previous
#include <cuda_runtime.h>
#include <math.h>

// Problem constants
#define NB   4
#define C    256
#define H    64
#define W    64
#define HW   4096
#define NPIX 16384
#define G    8
#define GC   32
#define P    9
#define NOFF 144
#define NMSK 72

// GEMM tiling (R6/R10 core — measured best)
#define BM 128
#define BN 128
#define BK 32
#define PADT 136

#define HALF_PIX (NPIX / 2)

// -------- scratch --------
__device__ float g_dw   [NPIX * C];
__device__ float g_xproj[NPIX * C];
__device__ float g_x1   [NPIX * C];
__device__ float g_off  [NPIX * NOFF];
__device__ float g_mlog [NPIX * NMSK];
__device__ float g_agg  [NPIX * C];

__device__ __forceinline__ unsigned f2tf(float f) {
    unsigned r; asm("cvt.rna.tf32.f32 %0, %1;" : "=r"(r) : "f"(f)); return r;
}

// ============================================================
// tf32 mma.sync GEMM core (R6: single-buffer, register prefetch).
// LAYOUT 0: A k-major source, PRE-OFFSET: element (k,m) at Asrc[k*HW + m]
// LAYOUT 1: A m-major source, PRE-OFFSET: element (m,k) at Asrc[m*256 + k]
// MODE   0: dense B0[256 x 256]
// MODE   1: B = concat(B0[256x144], B1[256x72]); cols >= 216 zero
// ============================================================
template<int LAYOUT, int MODE>
__device__ __forceinline__ void gemm_core(
    const float* __restrict__ Asrc,
    const float* __restrict__ B0, const float* __restrict__ B1,
    int bn, float acc[4][4][4])
{
    __shared__ float As[BK][PADT];
    __shared__ float Bs[BK][PADT];
    const int tid  = threadIdx.x;
    const int warp = tid >> 5, lane = tid & 31;
    const int gid  = lane >> 2, tig = lane & 3;
    const int wm   = warp >> 2, wn = warp & 3;

    float4 aReg[4], bReg[4];

    auto loadAB = [&](int k0) {
        #pragma unroll
        for (int i = 0; i < 4; i++) {
            if (LAYOUT == 0) {
                int idx = tid + 256 * i;
                int kr = idx >> 5, col = idx & 31;
                aReg[i] = *reinterpret_cast<const float4*>(
                    &Asrc[(size_t)(k0 + kr) * HW + col * 4]);
            } else {
                aReg[i] = *reinterpret_cast<const float4*>(
                    &Asrc[(size_t)(lane + 32 * i) * 256 + k0 + warp * 4]);
            }
        }
        #pragma unroll
        for (int i = 0; i < 4; i++) {
            int k = k0 + warp + 8 * i;
            if (MODE == 0) {
                bReg[i] = *reinterpret_cast<const float4*>(&B0[(size_t)k * 256 + bn + lane * 4]);
            } else {
                int c = bn + lane * 4;
                if (c < NOFF)
                    bReg[i] = *reinterpret_cast<const float4*>(&B0[(size_t)k * NOFF + c]);
                else if (c < NOFF + NMSK)
                    bReg[i] = *reinterpret_cast<const float4*>(&B1[(size_t)k * NMSK + c - NOFF]);
                else
                    bReg[i] = make_float4(0.f, 0.f, 0.f, 0.f);
            }
        }
    };

    auto stage = [&]() {
        #pragma unroll
        for (int i = 0; i < 4; i++) {
            if (LAYOUT == 0) {
                int idx = tid + 256 * i;
                int kr = idx >> 5, col = idx & 31;
                float4 t;
                t.x = __uint_as_float(f2tf(aReg[i].x));
                t.y = __uint_as_float(f2tf(aReg[i].y));
                t.z = __uint_as_float(f2tf(aReg[i].z));
                t.w = __uint_as_float(f2tf(aReg[i].w));
                *reinterpret_cast<float4*>(&As[kr][col * 4]) = t;
            } else {
                int m = lane + 32 * i;
                As[warp * 4 + 0][m] = __uint_as_float(f2tf(aReg[i].x));
                As[warp * 4 + 1][m] = __uint_as_float(f2tf(aReg[i].y));
                As[warp * 4 + 2][m] = __uint_as_float(f2tf(aReg[i].z));
                As[warp * 4 + 3][m] = __uint_as_float(f2tf(aReg[i].w));
            }
            float4 bt;
            bt.x = __uint_as_float(f2tf(bReg[i].x));
            bt.y = __uint_as_float(f2tf(bReg[i].y));
            bt.z = __uint_as_float(f2tf(bReg[i].z));
            bt.w = __uint_as_float(f2tf(bReg[i].w));
            *reinterpret_cast<float4*>(&Bs[warp + 8 * i][lane * 4]) = bt;
        }
    };

    loadAB(0);
    for (int k0 = 0; k0 < 256; k0 += BK) {
        __syncthreads();
        stage();
        __syncthreads();
        if (k0 + BK < 256) loadAB(k0 + BK);
        #pragma unroll
        for (int ks = 0; ks < 4; ks++) {
            unsigned a[4][4], b[4][2];
            #pragma unroll
            for (int mf = 0; mf < 4; mf++) {
                int m0 = wm * 64 + mf * 16;
                a[mf][0] = __float_as_uint(As[ks * 8 + tig    ][m0 + gid    ]);
                a[mf][1] = __float_as_uint(As[ks * 8 + tig    ][m0 + gid + 8]);
                a[mf][2] = __float_as_uint(As[ks * 8 + tig + 4][m0 + gid    ]);
                a[mf][3] = __float_as_uint(As[ks * 8 + tig + 4][m0 + gid + 8]);
            }
            #pragma unroll
            for (int nf = 0; nf < 4; nf++) {
                int n0 = wn * 32 + nf * 8;
                b[nf][0] = __float_as_uint(Bs[ks * 8 + tig    ][n0 + gid]);
                b[nf][1] = __float_as_uint(Bs[ks * 8 + tig + 4][n0 + gid]);
            }
            #pragma unroll
            for (int mf = 0; mf < 4; mf++)
                #pragma unroll
                for (int nf = 0; nf < 4; nf++)
                    asm volatile(
                        "mma.sync.aligned.m16n8k8.row.col.f32.tf32.tf32.f32 "
                        "{%0,%1,%2,%3},{%4,%5,%6,%7},{%8,%9},{%0,%1,%2,%3};"
                        : "+f"(acc[mf][nf][0]), "+f"(acc[mf][nf][1]),
                          "+f"(acc[mf][nf][2]), "+f"(acc[mf][nf][3])
                        : "r"(a[mf][0]), "r"(a[mf][1]), "r"(a[mf][2]), "r"(a[mf][3]),
                          "r"(b[nf][0]), "r"(b[nf][1]));
        }
    }
}

// ---- input projection (half-grid): x(NCHW) @ w_in + b_in -> g_xproj ----
extern "C" __global__ void __launch_bounds__(256)
gemm_in_kernel(const float* __restrict__ x,
               const float* __restrict__ Bw, const float* __restrict__ bias,
               int bm_base)
{
    float acc[4][4][4] = {};
    const int bm = bm_base + blockIdx.y * BM, bn = blockIdx.x * BN;
    const int n = bm >> 12, hw0 = bm & 4095;
    gemm_core<0, 0>(x + (size_t)n * C * HW + hw0, Bw, nullptr, bn, acc);

    const int lane = threadIdx.x & 31, warp = threadIdx.x >> 5;
    const int gid = lane >> 2, tig = lane & 3, wm = warp >> 2, wn = warp & 3;
    #pragma unroll
    for (int mf = 0; mf < 4; mf++) {
        int r0 = bm + wm * 64 + mf * 16 + gid;
        #pragma unroll
        for (int nf = 0; nf < 4; nf++) {
            int col = bn + wn * 32 + nf * 8 + 2 * tig;
            float bx = bias[col], by = bias[col + 1];
            float2 lo = {acc[mf][nf][0] + bx, acc[mf][nf][1] + by};
            float2 hi = {acc[mf][nf][2] + bx, acc[mf][nf][3] + by};
            *reinterpret_cast<float2*>(&g_xproj[(size_t)r0 * 256 + col])       = lo;
            *reinterpret_cast<float2*>(&g_xproj[(size_t)(r0 + 8) * 256 + col]) = hi;
        }
    }
}

// ---- fused offset+mask projection (half-grid) ----
extern "C" __global__ void __launch_bounds__(256)
gemm_offmask_kernel(const float* __restrict__ Bo, const float* __restrict__ Bm,
                    const float* __restrict__ bo, const float* __restrict__ bmk,
                    int bm_base)
{
    float acc[4][4][4] = {};
    const int bm = bm_base + blockIdx.y * BM, bn = blockIdx.x * BN;
    gemm_core<1, 1>(g_x1 + (size_t)bm * 256, Bo, Bm, bn, acc);

    const int lane = threadIdx.x & 31, warp = threadIdx.x >> 5;
    const int gid = lane >> 2, tig = lane & 3, wm = warp >> 2, wn = warp & 3;
    #pragma unroll
    for (int mf = 0; mf < 4; mf++) {
        int r0 = bm + wm * 64 + mf * 16 + gid;
        #pragma unroll
        for (int nf = 0; nf < 4; nf++) {
            int col = bn + wn * 32 + nf * 8 + 2 * tig;
            if (col >= NOFF + NMSK) continue;
            float bx, by; float *d0, *d1;
            if (col < NOFF) {
                bx = bo[col]; by = bo[col + 1];
                d0 = &g_off[(size_t)r0 * NOFF + col];
                d1 = &g_off[(size_t)(r0 + 8) * NOFF + col];
            } else {
                int mc = col - NOFF;
                bx = bmk[mc]; by = bmk[mc + 1];
                d0 = &g_mlog[(size_t)r0 * NMSK + mc];
                d1 = &g_mlog[(size_t)(r0 + 8) * NMSK + mc];
            }
            float2 lo = {acc[mf][nf][0] + bx, acc[mf][nf][1] + by};
            float2 hi = {acc[mf][nf][2] + bx, acc[mf][nf][3] + by};
            *reinterpret_cast<float2*>(d0) = lo;
            *reinterpret_cast<float2*>(d1) = hi;
        }
    }
}

// ---- output projection + bias + BN + SiLU -> NCHW (half-grid) ----
extern "C" __global__ void __launch_bounds__(256)
gemm_out_kernel(const float* __restrict__ Bw, const float* __restrict__ bias,
                const float* __restrict__ bn_g, const float* __restrict__ bn_b,
                const float* __restrict__ bn_mean, const float* __restrict__ bn_var,
                float* __restrict__ out, int bm_base)
{
    float acc[4][4][4] = {};
    const int bm = bm_base + blockIdx.y * BM, bn = blockIdx.x * BN;
    gemm_core<1, 0>(g_agg + (size_t)bm * 256, Bw, nullptr, bn, acc);

    const int lane = threadIdx.x & 31, warp = threadIdx.x >> 5;
    const int gid = lane >> 2, tig = lane & 3, wm = warp >> 2, wn = warp & 3;
    #pragma unroll
    for (int nf = 0; nf < 4; nf++) {
        int colb = bn + wn * 32 + nf * 8 + 2 * tig;
        #pragma unroll
        for (int j = 0; j < 2; j++) {
            int col = colb + j;
            float sc = bn_g[col] * rsqrtf(bn_var[col] + 1e-5f);
            float sh = bn_b[col] - bn_mean[col] * sc;
            float bo = bias[col];
            #pragma unroll
            for (int mf = 0; mf < 4; mf++) {
                #pragma unroll
                for (int h2 = 0; h2 < 2; h2++) {
                    int row = bm + wm * 64 + mf * 16 + gid + 8 * h2;
                    float v = acc[mf][nf][2 * h2 + j] + bo;
                    v = v * sc + sh;
                    v = v / (1.f + __expf(-v));
                    int n = row >> 12, hw = row & 4095;
                    out[((size_t)n * C + col) * HW + hw] = v;
                }
            }
        }
    }
}

// ============================================================
// Depthwise 3x3 conv, NCHW-native (plane_base for halves).
// ============================================================
extern "C" __global__ void __launch_bounds__(256)
dwconv_kernel(const float* __restrict__ x,
              const float* __restrict__ w_dw, const float* __restrict__ b_dw,
              int plane_base)
{
    __shared__ float sp[HW];
    const int plane = plane_base + blockIdx.x;
    const int n = plane >> 8, c = plane & 255;
    const int tid = threadIdx.x;
    const float* src = x + ((size_t)n * C + c) * HW;

    #pragma unroll
    for (int i = 0; i < 4; i++)
        *reinterpret_cast<float4*>(&sp[(tid + 256 * i) * 4]) =
            *reinterpret_cast<const float4*>(&src[(tid + 256 * i) * 4]);

    float wk[9];
    #pragma unroll
    for (int i = 0; i < 9; i++) wk[i] = w_dw[c * 9 + i];
    const float bb = b_dw[c];
    __syncthreads();

    float* dst = g_dw + ((size_t)n * C + c) * HW;
    #pragma unroll
    for (int i = 0; i < 16; i++) {
        int hw = tid + 256 * i;
        int h = hw >> 6, w = hw & 63;
        float acc = bb;
        #pragma unroll
        for (int ky = 0; ky < 3; ky++) {
            int yy = h + ky - 1;
            if (yy < 0 || yy > 63) continue;
            #pragma unroll
            for (int kx = 0; kx < 3; kx++) {
                int xx = w + kx - 1;
                if (xx < 0 || xx > 63) continue;
                acc += sp[yy * 64 + xx] * wk[ky * 3 + kx];
            }
        }
        dst[hw] = acc;
    }
}

// ============================================================
// LayerNorm + exact GELU + NCHW->NHWC transpose (blk_base halves).
// ============================================================
extern "C" __global__ void __launch_bounds__(256)
lnT_kernel(const float* __restrict__ ln_g, const float* __restrict__ ln_b,
           int blk_base)
{
    __shared__ float t[256][33];
    __shared__ float smean[32], sivar[32];
    const int blk = blk_base + blockIdx.x;
    const int n   = blk >> 7;
    const int hw0 = (blk & 127) * 32;
    const int tid = threadIdx.x;
    const int lane = tid & 31, wp = tid >> 5;

    const float* src = g_dw + (size_t)n * C * HW + hw0;
    #pragma unroll
    for (int r = 0; r < 32; r++) {
        int c = wp + 8 * r;
        t[c][lane] = src[(size_t)c * HW + lane];
    }
    __syncthreads();

    #pragma unroll
    for (int q = 0; q < 4; q++) {
        int p = wp * 4 + q;
        float s = 0.f;
        #pragma unroll
        for (int j = 0; j < 8; j++) s += t[lane + 32 * j][p];
        #pragma unroll
        for (int o = 16; o; o >>= 1) s += __shfl_xor_sync(0xffffffffu, s, o);
        float mu = s * (1.f / 256.f);
        float v = 0.f;
        #pragma unroll
        for (int j = 0; j < 8; j++) { float d = t[lane + 32 * j][p] - mu; v += d * d; }
        #pragma unroll
        for (int o = 16; o; o >>= 1) v += __shfl_xor_sync(0xffffffffu, v, o);
        if (lane == 0) { smean[p] = mu; sivar[p] = rsqrtf(v * (1.f / 256.f) + 1e-5f); }
    }
    __syncthreads();

    const float lg = ln_g[tid], lb = ln_b[tid];
    const size_t pixbase = (size_t)n * HW + hw0;
    #pragma unroll
    for (int p = 0; p < 32; p++) {
        float v = (t[tid][p] - smean[p]) * sivar[p] * lg + lb;
        float ge = 0.5f * v * (1.f + erff(v * 0.70710678118654752f));
        g_x1[(pixbase + p) * C + tid] = ge;
    }
}

// ============================================================
// Deformable sampling + softmax aggregation (pix_base for halves)
// ============================================================
extern "C" __global__ void __launch_bounds__(256)
sample_kernel(int pix_base)
{
    const int pix = pix_base + blockIdx.x;
    const int t   = threadIdx.x;
    const int g   = t >> 5, cc = t & 31;
    const int n = pix >> 12, hw = pix & 4095, h = hw >> 6, w = hw & 63;

    const float* ob = g_off  + (size_t)pix * NOFF + g * 18;
    const float* lb = g_mlog + (size_t)pix * NMSK + g * 9;

    float l[9], m = -1e30f;
    #pragma unroll
    for (int p = 0; p < 9; p++) { l[p] = lb[p]; m = fmaxf(m, l[p]); }
    float se = 0.f;
    #pragma unroll
    for (int p = 0; p < 9; p++) { l[p] = __expf(l[p] - m); se += l[p]; }
    const float inv = 1.f / se;

    const float* base = g_xproj + (size_t)n * HW * C + g * GC + cc;
    float acc = 0.f;
    #pragma unroll
    for (int p = 0; p < 9; p++) {
        float gx = (float)(w + (p / 3)) + ob[2 * p + 0];
        float gy = (float)(h + (p % 3)) + ob[2 * p + 1];
        float x0f = floorf(gx), y0f = floorf(gy);
        int   x0 = (int)x0f, y0 = (int)y0f;
        float wx = gx - x0f, wy = gy - y0f;
        float w00 = (1.f - wx) * (1.f - wy);
        float w10 = wx * (1.f - wy);
        float w01 = (1.f - wx) * wy;
        float w11 = wx * wy;
        bool yi0 = (y0     >= 1 && y0     <= 64);
        bool yi1 = (y0 + 1 >= 1 && y0 + 1 <= 64);
        bool xi0 = (x0     >= 1 && x0     <= 64);
        bool xi1 = (x0 + 1 >= 1 && x0 + 1 <= 64);
        float v00 = 0.f, v10 = 0.f, v01 = 0.f, v11 = 0.f;
        if (yi0 && xi0) v00 = base[((size_t)(y0 - 1) * 64 + (x0 - 1)) * C];
        if (yi0 && xi1) v10 = base[((size_t)(y0 - 1) * 64 + (x0    )) * C];
        if (yi1 && xi0) v01 = base[((size_t)(y0    ) * 64 + (x0 - 1)) * C];
        if (yi1 && xi1) v11 = base[((size_t)(y0    ) * 64 + (x0    )) * C];
        acc += (l[p] * inv) * (w00 * v00 + w10 * v10 + w01 * v01 + w11 * v11);
    }
    g_agg[(size_t)pix * C + t] = acc;
}

// ============================================================
// launch: two-stream half-pipeline (R10 footprint: 1 stream, 4 events)
//   s2: gin(H0) [evB0] -> gin(H1) -> [wait evL] off(H1) -> smp(H1) -> out(H1) [evE]
//   s0: dw -> ln [evL] -> off(H0) -> [wait evB0] smp(H0) -> out(H0); join evE
// ============================================================
extern "C" void kernel_launch(void* const* d_in, const int* in_sizes, int n_in,
                              void* d_out, int out_size)
{
    const float* x       = (const float*)d_in[0];
    const float* w_in    = (const float*)d_in[1];
    const float* b_in    = (const float*)d_in[2];
    const float* w_dw    = (const float*)d_in[3];
    const float* b_dw    = (const float*)d_in[4];
    const float* ln_g    = (const float*)d_in[5];
    const float* ln_b    = (const float*)d_in[6];
    const float* w_off   = (const float*)d_in[7];
    const float* b_off   = (const float*)d_in[8];
    const float* w_mask  = (const float*)d_in[9];
    const float* b_mask  = (const float*)d_in[10];
    const float* w_out   = (const float*)d_in[11];
    const float* b_out   = (const float*)d_in[12];
    const float* bn_g    = (const float*)d_in[13];
    const float* bn_b    = (const float*)d_in[14];
    const float* bn_mean = (const float*)d_in[15];
    const float* bn_var  = (const float*)d_in[16];
    float* out = (float*)d_out;

    static cudaStream_t s2 = nullptr;
    static cudaEvent_t evA = nullptr, evB0 = nullptr, evL = nullptr, evE = nullptr;
    if (!s2) {
        cudaStreamCreateWithFlags(&s2, cudaStreamNonBlocking);
        cudaEventCreateWithFlags(&evA, cudaEventDisableTiming);
        cudaEventCreateWithFlags(&evB0, cudaEventDisableTiming);
        cudaEventCreateWithFlags(&evL, cudaEventDisableTiming);
        cudaEventCreateWithFlags(&evE, cudaEventDisableTiming);
    }

    const dim3 gInHalf(C / BN, HALF_PIX / BM);   // (2, 64)
    const dim3 gOffHalf(2, HALF_PIX / BM);       // (2, 64)
    const dim3 gOutHalf(C / BN, HALF_PIX / BM);  // (2, 64)

    // fork: gemm_in (two halves) depends only on x
    cudaEventRecord(evA, 0);
    cudaStreamWaitEvent(s2, evA, 0);
    gemm_in_kernel<<<gInHalf, 256, 0, s2>>>(x, w_in, b_in, 0);
    cudaEventRecord(evB0, s2);
    gemm_in_kernel<<<gInHalf, 256, 0, s2>>>(x, w_in, b_in, HALF_PIX);

    // s0: dw branch (full)
    dwconv_kernel<<<NB * C, 256>>>(x, w_dw, b_dw, 0);
    lnT_kernel   <<<NPIX / 32, 256>>>(ln_g, ln_b, 0);
    cudaEventRecord(evL, 0);

    // s0: half 0 chain
    gemm_offmask_kernel<<<gOffHalf, 256>>>(w_off, w_mask, b_off, b_mask, 0);
    cudaStreamWaitEvent(0, evB0, 0);
    sample_kernel  <<<HALF_PIX, 256>>>(0);
    gemm_out_kernel<<<gOutHalf, 256>>>(w_out, b_out, bn_g, bn_b, bn_mean, bn_var,
                                       out, 0);

    // s2: half 1 chain (gin(H1) already in-stream)
    cudaStreamWaitEvent(s2, evL, 0);
    gemm_offmask_kernel<<<gOffHalf, 256, 0, s2>>>(w_off, w_mask, b_off, b_mask, HALF_PIX);
    sample_kernel  <<<HALF_PIX, 256, 0, s2>>>(HALF_PIX);
    gemm_out_kernel<<<gOutHalf, 256, 0, s2>>>(w_out, b_out, bn_g, bn_b, bn_mean, bn_var,
                                              out, HALF_PIX);
    cudaEventRecord(evE, s2);

    // join
    cudaStreamWaitEvent(0, evE, 0);
}